// round 15
// baseline (speedup 1.0000x reference)
#include <cuda_runtime.h>
#include <cuda_fp16.h>
#include <cstdint>

#define BB 4
#define LL 1024
#define DD 512
#define HH 8
#define HDIM 64
#define FF 2048
#define NLAYERS 6
#define ROWS (BB*LL)        // 4096
#define KVW (NLAYERS*2*DD)  // 6144

// ---------------- scratch (no allocation allowed) ----------------
__device__ float g_x[ROWS*DD];
__device__ float g_t[ROWS*DD];
__device__ float g_bkv[KVW];
__device__ int   g_kt[4];
__device__ __half g_xh[ROWS*DD];
__device__ __half g_kh[ROWS*DD];
__device__ __half g_ah[ROWS*DD];
__device__ __half g_hh[ROWS*FF];
__device__ __half g_kvp[(size_t)ROWS*KVW];     // all-layer K|V projections
__device__ __half g_wqh[NLAYERS*DD*DD];
__device__ __half g_woh[NLAYERS*DD*DD];
__device__ __half g_wkvh[NLAYERS*2*DD*DD];     // interleaved [li][K|V]
__device__ __half g_w1h[NLAYERS*FF*DD];
__device__ __half g_w2h[NLAYERS*FF*DD];

// ---------------- helpers ----------------
__device__ __forceinline__ uint32_t smem_u32(const void* p) {
    uint32_t a;
    asm("{ .reg .u64 t; cvta.to.shared.u64 t, %1; cvt.u32.u64 %0, t; }" : "=r"(a) : "l"(p));
    return a;
}
__device__ __forceinline__ void cp_async16(uint32_t dst, const void* src) {
    asm volatile("cp.async.cg.shared.global [%0], [%1], 16;" :: "r"(dst), "l"(src) : "memory");
}
__device__ __forceinline__ void cp_commit() {
    asm volatile("cp.async.commit_group;" ::: "memory");
}
template<int N>
__device__ __forceinline__ void cp_wait() {
    asm volatile("cp.async.wait_group %0;" :: "n"(N) : "memory");
}
__device__ __forceinline__ void ldm_x4(uint32_t* r, uint32_t addr) {
    asm volatile("ldmatrix.sync.aligned.m8n8.x4.shared.b16 {%0,%1,%2,%3}, [%4];"
                 : "=r"(r[0]), "=r"(r[1]), "=r"(r[2]), "=r"(r[3]) : "r"(addr));
}
__device__ __forceinline__ void ldm_x4_t(uint32_t* r, uint32_t addr) {
    asm volatile("ldmatrix.sync.aligned.m8n8.x4.trans.shared.b16 {%0,%1,%2,%3}, [%4];"
                 : "=r"(r[0]), "=r"(r[1]), "=r"(r[2]), "=r"(r[3]) : "r"(addr));
}
__device__ __forceinline__ void mma16816(float* c, const uint32_t* a, const uint32_t* b) {
    asm volatile(
        "mma.sync.aligned.m16n8k16.row.col.f32.f16.f16.f32 "
        "{%0,%1,%2,%3}, {%4,%5,%6,%7}, {%8,%9}, {%0,%1,%2,%3};"
        : "+f"(c[0]), "+f"(c[1]), "+f"(c[2]), "+f"(c[3])
        : "r"(a[0]), "r"(a[1]), "r"(a[2]), "r"(a[3]), "r"(b[0]), "r"(b[1]));
}
__device__ __forceinline__ uint32_t packh2(float a, float b) {
    __half2 h = __floats2half2_rn(a, b);
    return *(uint32_t*)&h;
}
// PDL primitives (sm_90+; family-safe PTX)
__device__ __forceinline__ void pdl_wait() {
    asm volatile("griddepcontrol.wait;" ::: "memory");
}
__device__ __forceinline__ void pdl_trigger() {
    asm volatile("griddepcontrol.launch_dependents;");
}

// ---------------- merged startup kernel ----------------
// float4-unit job ranges
#define PN0 393216                    // wq -> fp16
#define PN1 (PN0 + 393216)            // wo
#define PN2 (PN1 + 1572864)           // w1
#define PN3 (PN2 + 1572864)           // w2
#define PN4 (PN3 + 524288)            // key -> fp16
#define PN5 (PN4 + 524288)            // query -> fp32 + fp16
#define PN6 (PN5 + 786432)            // wkv interleave fp16
#define PREP_F4_BLOCKS (PN6 / 256)    // 22528
#define PREP_BLOCKS (PREP_F4_BLOCKS + 28)

__device__ __forceinline__ void cvt_f4(const float* s, __half* d, long off) {
    float4 v = ((const float4*)s)[off];
    __half2* d2 = (__half2*)d + off * 2;
    d2[0] = __floats2half2_rn(v.x, v.y);
    d2[1] = __floats2half2_rn(v.z, v.w);
}

__global__ void prep_kernel(const float* __restrict__ wq, const float* __restrict__ wo,
                            const float* __restrict__ w1, const float* __restrict__ w2,
                            const float* __restrict__ key, const float* __restrict__ query,
                            const float* __restrict__ wk, const float* __restrict__ wv,
                            const float* __restrict__ bk, const float* __restrict__ bv,
                            const float* __restrict__ kmask,
                            __half* dwq, __half* dwo, __half* dw1, __half* dw2,
                            __half* dkey, float* dpx, __half* dpxh, __half* dwkv,
                            float* dbkv, int* dkt) {
    const int tid = threadIdx.x;
    if (blockIdx.x < PREP_F4_BLOCKS) {
        long i = (long)blockIdx.x * 256 + tid;
        if (i < PN0)      cvt_f4(wq, dwq, i);
        else if (i < PN1) cvt_f4(wo, dwo, i - PN0);
        else if (i < PN2) cvt_f4(w1, dw1, i - PN1);
        else if (i < PN3) cvt_f4(w2, dw2, i - PN2);
        else if (i < PN4) cvt_f4(key, dkey, i - PN3);
        else if (i < PN5) {
            long off = i - PN4;
            float4 v = ((const float4*)query)[off];
            ((float4*)dpx)[off] = v;
            __half2* d2 = (__half2*)dpxh + off * 2;
            d2[0] = __floats2half2_rn(v.x, v.y);
            d2[1] = __floats2half2_rn(v.z, v.w);
        } else {
            long off = i - PN5;
            int li = (int)(off / 131072), rem = (int)(off % 131072);
            const float4* src = (rem < 65536)
                ? ((const float4*)wk + (size_t)li * 65536 + rem)
                : ((const float4*)wv + (size_t)li * 65536 + (rem - 65536));
            float4 v = *src;
            __half2* d2 = (__half2*)dwkv + ((size_t)li * 131072 + rem) * 2;
            d2[0] = __floats2half2_rn(v.x, v.y);
            d2[1] = __floats2half2_rn(v.z, v.w);
        }
    } else {
        __shared__ float red[8];
        int mb = blockIdx.x - PREP_F4_BLOCKS;    // 0..27
        if (mb < 24) {
            int i = mb * 256 + tid;
            int li = i >> 10, r = i & 1023;
            dbkv[i] = (r < 512) ? bk[li * 512 + r] : bv[li * 512 + (r - 512)];
        } else {
            int b = mb - 24;
            float s = 0.f;
            for (int i = tid; i < LL; i += 256) s += kmask[b * LL + i];
#pragma unroll
            for (int o = 16; o > 0; o >>= 1) s += __shfl_down_sync(0xffffffffu, s, o);
            if ((tid & 31) == 0) red[tid >> 5] = s;
            __syncthreads();
            if (tid == 0) {
                float t = 0.f;
                for (int i = 0; i < 8; i++) t += red[i];
                dkt[b] = ((int)(t + 0.5f) + 63) >> 6;
            }
        }
    }
}

// ---------------- HMMA fp16 GEMM (3-stage cp.async, PDL-aware) ----------------
#define GSTR 40
#define STAGE_HALFS (128 * GSTR * 2)
#define GS3 (3 * STAGE_HALFS * 2)     // 61440 bytes dynamic smem

template<bool RELU, bool OUTH, bool ADDRES>
__global__ __launch_bounds__(256)
void gemm_tc(const __half* __restrict__ A, const __half* __restrict__ Wt,
             const float* __restrict__ bias, void* __restrict__ Cout,
             int M, int N, int K, int preB,
             const float* __restrict__ xres, const float* __restrict__ qmask) {
    extern __shared__ char gsm[];
    const uint32_t sb = smem_u32(gsm);
    const int tid = threadIdx.x;
    const int wid = tid >> 5;
    const int lane = tid & 31;
    const int m0 = blockIdx.y * 128;
    const int n0 = blockIdx.x * 128;

    const int mwb = (wid >> 1) * 32;
    const int nwb = (wid & 1) * 64;

    float c[2][8][4];
#pragma unroll
    for (int mt = 0; mt < 2; mt++)
#pragma unroll
        for (int nt = 0; nt < 8; nt++)
#pragma unroll
            for (int i = 0; i < 4; i++) c[mt][nt][i] = 0.f;

    const int nch = K >> 5;

    auto load_A = [&](int kc, int stage) {
        const uint32_t sbase = sb + stage * STAGE_HALFS * 2;
#pragma unroll
        for (int it = 0; it < 2; it++) {
            int idx = tid + it * 256;
            int r = idx >> 2, cseg = idx & 3;
            cp_async16(sbase + (r * GSTR + cseg * 8) * 2,
                       A + (size_t)(m0 + r) * K + kc * 32 + cseg * 8);
        }
        cp_commit();
    };
    auto load_B = [&](int kc, int stage) {
        const uint32_t sbase = sb + stage * STAGE_HALFS * 2 + 128 * GSTR * 2;
#pragma unroll
        for (int it = 0; it < 2; it++) {
            int idx = tid + it * 256;
            int r = idx >> 2, cseg = idx & 3;
            cp_async16(sbase + (r * GSTR + cseg * 8) * 2,
                       Wt + (size_t)(n0 + r) * K + kc * 32 + cseg * 8);
        }
        cp_commit();
    };
    auto load_stage = [&](int kc, int stage) {
        const uint32_t sbase = sb + stage * STAGE_HALFS * 2;
#pragma unroll
        for (int it = 0; it < 4; it++) {
            int idx = tid + it * 256;
            int r = (idx & 511) >> 2;
            int cseg = idx & 3;
            const __half* src;
            uint32_t dst;
            if (idx < 512) {
                src = A + (size_t)(m0 + r) * K + kc * 32 + cseg * 8;
                dst = sbase + (r * GSTR + cseg * 8) * 2;
            } else {
                src = Wt + (size_t)(n0 + r) * K + kc * 32 + cseg * 8;
                dst = sbase + (128 * GSTR + r * GSTR + cseg * 8) * 2;
            }
            cp_async16(dst, src);
        }
        cp_commit();
    };

    // PDL: weights (from prep, >=2 kernels back) may be prefetched pre-wait;
    // kv-gemm's weights come from its direct predecessor -> wait first.
    if (preB) {
        load_B(0, 0); load_B(1, 1);
        pdl_wait(); pdl_trigger();
        load_A(0, 0); load_A(1, 1);
    } else {
        pdl_wait(); pdl_trigger();
        load_B(0, 0); load_B(1, 1);
        load_A(0, 0); load_A(1, 1);
    }
    // groups in flight: [B0, B1, A0, A1]

    for (int kc = 0; kc < nch; kc++) {
        const int st = kc % 3;
        if (kc + 1 < nch) cp_wait<1>();
        else              cp_wait<0>();
        __syncthreads();
        if (kc + 2 < nch) load_stage(kc + 2, (kc + 2) % 3);

        const uint32_t Ab = sb + st * STAGE_HALFS * 2;
        const uint32_t Bb = Ab + 128 * GSTR * 2;

#pragma unroll
        for (int ks = 0; ks < 2; ks++) {
            uint32_t afr[2][4], bfr[4][4];
#pragma unroll
            for (int mt = 0; mt < 2; mt++) {
                uint32_t addr = Ab + (((mwb + mt * 16 + (lane & 15)) * GSTR)
                                      + ks * 16 + ((lane >> 4) << 3)) * 2;
                ldm_x4(afr[mt], addr);
            }
#pragma unroll
            for (int np = 0; np < 4; np++) {
                uint32_t addr = Bb + (((nwb + np * 16 + (lane & 7) + ((lane >> 4) << 3)) * GSTR)
                                      + ks * 16 + (((lane >> 3) & 1) << 3)) * 2;
                ldm_x4(bfr[np], addr);
            }
#pragma unroll
            for (int mt = 0; mt < 2; mt++)
#pragma unroll
                for (int nt = 0; nt < 8; nt++)
                    mma16816(c[mt][nt], afr[mt], bfr[nt >> 1] + (nt & 1) * 2);
        }
    }

#pragma unroll
    for (int mt = 0; mt < 2; mt++) {
        const int r0 = m0 + mwb + mt * 16 + (lane >> 2);
        float qm0 = 0.f, qm1 = 0.f;
        if (ADDRES) { qm0 = qmask[r0]; qm1 = qmask[r0 + 8]; }
#pragma unroll
        for (int nt = 0; nt < 8; nt++) {
            int col = n0 + nwb + nt * 8 + (lane & 3) * 2;
            float bv0 = bias[col], bv1 = bias[col + 1];
            float v0 = c[mt][nt][0] + bv0;
            float v1 = c[mt][nt][1] + bv1;
            float v2 = c[mt][nt][2] + bv0;
            float v3 = c[mt][nt][3] + bv1;
            if (RELU) {
                v0 = fmaxf(v0, 0.f); v1 = fmaxf(v1, 0.f);
                v2 = fmaxf(v2, 0.f); v3 = fmaxf(v3, 0.f);
            }
            if (ADDRES) {
                float2 x0 = *(const float2*)(xres + (size_t)r0 * N + col);
                float2 x1 = *(const float2*)(xres + (size_t)(r0 + 8) * N + col);
                v0 = v0 * qm0 + x0.x; v1 = v1 * qm0 + x0.y;
                v2 = v2 * qm1 + x1.x; v3 = v3 * qm1 + x1.y;
            }
            if (OUTH) {
                __half* base = (__half*)Cout;
                *(__half2*)(base + (size_t)r0 * N + col)       = __floats2half2_rn(v0, v1);
                *(__half2*)(base + (size_t)(r0 + 8) * N + col) = __floats2half2_rn(v2, v3);
            } else {
                float* base = (float*)Cout;
                *(float2*)(base + (size_t)r0 * N + col)       = make_float2(v0, v1);
                *(float2*)(base + (size_t)(r0 + 8) * N + col) = make_float2(v2, v3);
            }
        }
    }
}

// ---------------- HMMA flash attention with fused Q projection (PDL-aware) ----------------
#define ATS 72

__global__ __launch_bounds__(128)
void attn_tc(const __half* __restrict__ xh, const __half* __restrict__ wqh,
             const float* __restrict__ bqp,
             const __half* __restrict__ kb0, const __half* __restrict__ vb0, int kvs,
             const int* __restrict__ ktarr, const float* __restrict__ kmask,
             __half* __restrict__ out) {
    __shared__ __half Ks[2][64 * ATS];
    __shared__ __half Vs[2][64 * ATS];
    __shared__ float MD[2][64];

    const int q0 = blockIdx.x * 64;
    const int h  = blockIdx.y;
    const int b  = blockIdx.z;
    const int tid = threadIdx.x;
    const int wid = tid >> 5;
    const int lane = tid & 31;
    const int mwb = wid * 16;
    const float scl = 0.125f;

    const uint32_t sK0 = smem_u32(Ks);
    const uint32_t sV0 = smem_u32(Vs);

    const __half* xb = xh + ((size_t)(b * LL + q0)) * DD;
    const __half* wb = wqh + (size_t)h * HDIM * DD;

    auto load_X = [&](int kc, int st) {
        const uint32_t sX = sK0 + st * 64 * ATS * 2;
#pragma unroll
        for (int i = 0; i < 2; i++) {
            int idx = tid + i * 128;
            int r = idx >> 2, c8 = (idx & 3) * 8;
            cp_async16(sX + (r * ATS + c8) * 2, xb + (size_t)r * DD + kc * 32 + c8);
        }
    };
    auto load_W = [&](int kc, int st) {
        const uint32_t sW = sV0 + st * 64 * ATS * 2;
#pragma unroll
        for (int i = 0; i < 2; i++) {
            int idx = tid + i * 128;
            int r = idx >> 2, c8 = (idx & 3) * 8;
            cp_async16(sW + (r * ATS + c8) * 2, wb + (size_t)r * DD + kc * 32 + c8);
        }
    };

    // Pre-wait: NT + Wq prefetch (prep outputs, >=2 kernels back -> complete)
    const int NT = ktarr[b];
    load_W(0, 0); cp_commit();      // g0
    load_W(1, 1); cp_commit();      // g1
    pdl_wait(); pdl_trigger();
    load_X(0, 0); cp_commit();      // g2

    float qa[8][4];
#pragma unroll
    for (int nt = 0; nt < 8; nt++)
#pragma unroll
        for (int i = 0; i < 4; i++) qa[nt][i] = 0.f;

    for (int kc = 0; kc < 16; kc++) {
        const int st = kc & 1;
        __syncthreads();
        if (kc + 1 < 16) {
            load_X(kc + 1, st ^ 1);
            if (kc + 1 >= 2) load_W(kc + 1, st ^ 1);
            cp_commit();
            cp_wait<1>();
        } else {
            cp_wait<0>();
        }
        __syncthreads();
        const uint32_t sX = sK0 + st * 64 * ATS * 2;
        const uint32_t sW = sV0 + st * 64 * ATS * 2;
#pragma unroll
        for (int ks = 0; ks < 2; ks++) {
            uint32_t ax[4], bw[4][4];
            {
                uint32_t addr = sX + (((mwb + (lane & 15)) * ATS) + ks * 16 + ((lane >> 4) << 3)) * 2;
                ldm_x4(ax, addr);
            }
#pragma unroll
            for (int np = 0; np < 4; np++) {
                uint32_t addr = sW + (((np * 16 + (lane & 7) + ((lane >> 4) << 3)) * ATS)
                                      + ks * 16 + (((lane >> 3) & 1) << 3)) * 2;
                ldm_x4(bw[np], addr);
            }
#pragma unroll
            for (int nt = 0; nt < 8; nt++)
                mma16816(qa[nt], ax, bw[nt >> 1] + (nt & 1) * 2);
        }
    }

    // bias + scale, repack C-frags as A-frags
    uint32_t aq[4][4];
    {
        const int c0i = (lane & 3) * 2;
#pragma unroll
        for (int nt = 0; nt < 8; nt++) {
            int col = h * HDIM + nt * 8 + c0i;
            float b0 = bqp[col], b1 = bqp[col + 1];
            qa[nt][0] = (qa[nt][0] + b0) * scl;
            qa[nt][1] = (qa[nt][1] + b1) * scl;
            qa[nt][2] = (qa[nt][2] + b0) * scl;
            qa[nt][3] = (qa[nt][3] + b1) * scl;
        }
#pragma unroll
        for (int kc = 0; kc < 4; kc++) {
            aq[kc][0] = packh2(qa[2 * kc][0], qa[2 * kc][1]);
            aq[kc][1] = packh2(qa[2 * kc][2], qa[2 * kc][3]);
            aq[kc][2] = packh2(qa[2 * kc + 1][0], qa[2 * kc + 1][1]);
            aq[kc][3] = packh2(qa[2 * kc + 1][2], qa[2 * kc + 1][3]);
        }
    }
    __syncthreads();     // Q-proj reads done before K/V overwrite

    // ---- flash attention main loop ----
    auto load_kv = [&](int kt, int st) {
        const int k0 = kt * 64;
        const __half* kb = kb0 + ((size_t)(b * LL + k0)) * kvs + h * HDIM;
        const __half* vb = vb0 + ((size_t)(b * LL + k0)) * kvs + h * HDIM;
        const uint32_t sK = sK0 + st * 64 * ATS * 2;
        const uint32_t sV = sV0 + st * 64 * ATS * 2;
#pragma unroll
        for (int i = 0; i < 8; i++) {
            int idx = tid + i * 128;
            int r = (idx & 511) >> 3, c8 = (idx & 7) * 8;
            if (idx < 512) cp_async16(sK + (r * ATS + c8) * 2, kb + (size_t)r * kvs + c8);
            else           cp_async16(sV + (r * ATS + c8) * 2, vb + (size_t)r * kvs + c8);
        }
        if (tid < 64) MD[st][tid] = (kmask[b * LL + k0 + tid] == 0.f) ? -1e30f : 0.f;
        cp_commit();
    };

    load_kv(0, 0);

    float co[8][4];
#pragma unroll
    for (int nt = 0; nt < 8; nt++)
#pragma unroll
        for (int i = 0; i < 4; i++) co[nt][i] = 0.f;
    float m0 = -1e30f, m1 = -1e30f, l0 = 0.f, l1 = 0.f;
    const int c0 = (lane & 3) * 2;

    for (int kt = 0; kt < NT; kt++) {
        const int st = kt & 1;
        __syncthreads();
        if (kt + 1 < NT) {
            load_kv(kt + 1, st ^ 1);
            cp_wait<1>();
        } else {
            cp_wait<0>();
        }
        __syncthreads();

        const uint32_t sK = sK0 + st * 64 * ATS * 2;
        const uint32_t sV = sV0 + st * 64 * ATS * 2;

        // ---- S = Q K^T ----
        float cs[8][4];
#pragma unroll
        for (int nt = 0; nt < 8; nt++)
#pragma unroll
            for (int i = 0; i < 4; i++) cs[nt][i] = 0.f;
#pragma unroll
        for (int kc = 0; kc < 4; kc++) {
            uint32_t bk[4][4];
#pragma unroll
            for (int np = 0; np < 4; np++) {
                uint32_t addr = sK + (((np * 16 + (lane & 7) + ((lane >> 4) << 3)) * ATS)
                                      + kc * 16 + (((lane >> 3) & 1) << 3)) * 2;
                ldm_x4(bk[np], addr);
            }
#pragma unroll
            for (int nt = 0; nt < 8; nt++)
                mma16816(cs[nt], aq[kc], bk[nt >> 1] + (nt & 1) * 2);
        }

        // ---- online softmax ----
        float sv[8][4];
        float mx0 = -1e30f, mx1 = -1e30f;
#pragma unroll
        for (int nt = 0; nt < 8; nt++) {
            float a0 = MD[st][nt * 8 + c0], a1 = MD[st][nt * 8 + c0 + 1];
            sv[nt][0] = cs[nt][0] + a0;
            sv[nt][1] = cs[nt][1] + a1;
            sv[nt][2] = cs[nt][2] + a0;
            sv[nt][3] = cs[nt][3] + a1;
            mx0 = fmaxf(mx0, fmaxf(sv[nt][0], sv[nt][1]));
            mx1 = fmaxf(mx1, fmaxf(sv[nt][2], sv[nt][3]));
        }
        mx0 = fmaxf(mx0, __shfl_xor_sync(0xffffffffu, mx0, 1));
        mx0 = fmaxf(mx0, __shfl_xor_sync(0xffffffffu, mx0, 2));
        mx1 = fmaxf(mx1, __shfl_xor_sync(0xffffffffu, mx1, 1));
        mx1 = fmaxf(mx1, __shfl_xor_sync(0xffffffffu, mx1, 2));
        float mn0 = fmaxf(m0, mx0), mn1 = fmaxf(m1, mx1);
        float cr0 = __expf(m0 - mn0), cr1 = __expf(m1 - mn1);
        l0 *= cr0; l1 *= cr1;
#pragma unroll
        for (int nt = 0; nt < 8; nt++) {
            co[nt][0] *= cr0; co[nt][1] *= cr0;
            co[nt][2] *= cr1; co[nt][3] *= cr1;
        }
        float ps0 = 0.f, ps1 = 0.f;
        uint32_t ph[8][2];
#pragma unroll
        for (int nt = 0; nt < 8; nt++) {
            float p0 = __expf(sv[nt][0] - mn0);
            float p1 = __expf(sv[nt][1] - mn0);
            float p2 = __expf(sv[nt][2] - mn1);
            float p3 = __expf(sv[nt][3] - mn1);
            ps0 += p0 + p1; ps1 += p2 + p3;
            ph[nt][0] = packh2(p0, p1);
            ph[nt][1] = packh2(p2, p3);
        }
        ps0 += __shfl_xor_sync(0xffffffffu, ps0, 1);
        ps0 += __shfl_xor_sync(0xffffffffu, ps0, 2);
        ps1 += __shfl_xor_sync(0xffffffffu, ps1, 1);
        ps1 += __shfl_xor_sync(0xffffffffu, ps1, 2);
        l0 += ps0; l1 += ps1;
        m0 = mn0; m1 = mn1;

        // ---- O += P V ----
#pragma unroll
        for (int kc = 0; kc < 4; kc++) {
            uint32_t bv[4][4];
#pragma unroll
            for (int np = 0; np < 4; np++) {
                uint32_t addr = sV + (((kc * 16 + (lane & 7) + (((lane >> 3) & 1) << 3)) * ATS)
                                      + np * 16 + ((lane >> 4) << 3)) * 2;
                ldm_x4_t(bv[np], addr);
            }
            uint32_t a[4] = { ph[2 * kc][0], ph[2 * kc][1], ph[2 * kc + 1][0], ph[2 * kc + 1][1] };
#pragma unroll
            for (int nt = 0; nt < 8; nt++)
                mma16816(co[nt], a, bv[nt >> 1] + (nt & 1) * 2);
        }
    }

    float inv0 = 1.f / l0, inv1 = 1.f / l1;
    __half* ob = out + ((size_t)(b * LL + q0 + mwb)) * DD + h * HDIM;
    const int r0 = lane >> 2;
#pragma unroll
    for (int nt = 0; nt < 8; nt++) {
        int col = nt * 8 + c0;
        *(__half2*)(ob + (size_t)r0 * DD + col)       = __floats2half2_rn(co[nt][0] * inv0, co[nt][1] * inv0);
        *(__half2*)(ob + (size_t)(r0 + 8) * DD + col) = __floats2half2_rn(co[nt][2] * inv1, co[nt][3] * inv1);
    }
}

// ---------------- LayerNorm (PDL-aware; gamma/beta prefetched pre-wait) ----------------
__global__ void ln_kernel(const float* __restrict__ y,
                          const float* __restrict__ gam, const float* __restrict__ bet,
                          float* __restrict__ xout, __half* __restrict__ xouth) {
    __shared__ float red[4];
    const int row = blockIdx.x;
    const int tid = threadIdx.x;

    float gv[4], bv[4];
#pragma unroll
    for (int i = 0; i < 4; i++) {
        int idx = tid + i * 128;
        gv[i] = gam[idx];
        bv[i] = bet[idx];
    }
    pdl_wait(); pdl_trigger();

    const float* yr = y + (size_t)row * DD;
    float vals[4];
    float s = 0.f;
#pragma unroll
    for (int i = 0; i < 4; i++) {
        int idx = tid + i * 128;
        vals[i] = yr[idx];
        s += vals[i];
    }
#pragma unroll
    for (int off = 16; off > 0; off >>= 1) s += __shfl_down_sync(0xffffffffu, s, off);
    if ((tid & 31) == 0) red[tid >> 5] = s;
    __syncthreads();
    float mean = (red[0] + red[1] + red[2] + red[3]) * (1.f / DD);

    float s2 = 0.f;
#pragma unroll
    for (int i = 0; i < 4; i++) {
        float d = vals[i] - mean;
        s2 += d * d;
    }
    __syncthreads();
#pragma unroll
    for (int off = 16; off > 0; off >>= 1) s2 += __shfl_down_sync(0xffffffffu, s2, off);
    if ((tid & 31) == 0) red[tid >> 5] = s2;
    __syncthreads();
    float var = (red[0] + red[1] + red[2] + red[3]) * (1.f / DD);
    float inv = rsqrtf(var + 1e-5f);

    float* xo = xout + (size_t)row * DD;
    __half* xoh = xouth + (size_t)row * DD;
#pragma unroll
    for (int i = 0; i < 4; i++) {
        int idx = tid + i * 128;
        float r = (vals[i] - mean) * inv * gv[i] + bv[i];
        xo[idx] = r;
        xoh[idx] = __float2half(r);
    }
}

// ---------------- PDL launcher ----------------
template<typename KT, typename... Args>
static inline void launch_pdl(KT kern, dim3 grid, dim3 block, size_t smem, Args... args) {
    cudaLaunchConfig_t cfg = {};
    cfg.gridDim = grid;
    cfg.blockDim = block;
    cfg.dynamicSmemBytes = smem;
    cfg.stream = 0;
    cudaLaunchAttribute at[1];
    at[0].id = cudaLaunchAttributeProgrammaticStreamSerialization;
    at[0].val.programmaticStreamSerializationAllowed = 1;
    cfg.attrs = at;
    cfg.numAttrs = 1;
    cudaLaunchKernelEx(&cfg, kern, args...);
}

// ---------------- launch ----------------
extern "C" void kernel_launch(void* const* d_in, const int* in_sizes, int n_in,
                              void* d_out, int out_size) {
    const float* query = (const float*)d_in[0];
    const float* key   = (const float*)d_in[1];
    const float* qmask = (const float*)d_in[2];
    const float* kmask = (const float*)d_in[3];
    const float* bq = (const float*)d_in[5];
    const float* bk = (const float*)d_in[7];
    const float* bv = (const float*)d_in[9];
    const float* bo = (const float*)d_in[11];
    const float* b1 = (const float*)d_in[13];
    const float* b2 = (const float*)d_in[15];
    const float* ln1g = (const float*)d_in[16];
    const float* ln1b = (const float*)d_in[17];
    const float* ln2g = (const float*)d_in[18];
    const float* ln2b = (const float*)d_in[19];
    float* out = (float*)d_out;

    float *px, *pt, *pbkv;
    int* pkt;
    __half *pxh, *pkh, *pah, *phh, *pkv;
    __half *wq, *wo, *wkv, *w1, *w2;
    cudaGetSymbolAddress((void**)&px, g_x);
    cudaGetSymbolAddress((void**)&pt, g_t);
    cudaGetSymbolAddress((void**)&pbkv, g_bkv);
    cudaGetSymbolAddress((void**)&pkt, g_kt);
    cudaGetSymbolAddress((void**)&pxh, g_xh);
    cudaGetSymbolAddress((void**)&pkh, g_kh);
    cudaGetSymbolAddress((void**)&pah, g_ah);
    cudaGetSymbolAddress((void**)&phh, g_hh);
    cudaGetSymbolAddress((void**)&pkv, g_kvp);
    cudaGetSymbolAddress((void**)&wq, g_wqh);
    cudaGetSymbolAddress((void**)&wo, g_woh);
    cudaGetSymbolAddress((void**)&wkv, g_wkvh);
    cudaGetSymbolAddress((void**)&w1, g_w1h);
    cudaGetSymbolAddress((void**)&w2, g_w2h);

    cudaFuncSetAttribute(gemm_tc<false, true, false>, cudaFuncAttributeMaxDynamicSharedMemorySize, GS3);
    cudaFuncSetAttribute(gemm_tc<false, false, true>, cudaFuncAttributeMaxDynamicSharedMemorySize, GS3);
    cudaFuncSetAttribute(gemm_tc<true, true, false>,  cudaFuncAttributeMaxDynamicSharedMemorySize, GS3);

    // ---- startup: single merged prep kernel (no PDL attr; implicit trigger at completion) ----
    prep_kernel<<<PREP_BLOCKS, 256>>>(
        (const float*)d_in[4], (const float*)d_in[10], (const float*)d_in[12],
        (const float*)d_in[14], key, query,
        (const float*)d_in[6], (const float*)d_in[8], bk, bv, kmask,
        wq, wo, w1, w2, pkh, px, pxh, wkv, pbkv, pkt);

    const dim3 gemm_blk(256);
    const dim3 gD(DD / 128, ROWS / 128);
    const dim3 gF(FF / 128, ROWS / 128);
    const dim3 gKV(KVW / 128, ROWS / 128);
    const dim3 gAttn(LL / 64, HH, BB);

    // KV projection: weights come from direct predecessor (prep) -> preB=0
    launch_pdl(gemm_tc<false, true, false>, gKV, gemm_blk, GS3,
               (const __half*)pkh, (const __half*)wkv, (const float*)pbkv, (void*)pkv,
               ROWS, KVW, DD, 0, (const float*)nullptr, (const float*)nullptr);

    for (int li = 0; li < NLAYERS; li++) {
        const size_t wED = (size_t)li * DD * DD;
        const size_t wFD = (size_t)li * FF * DD;

        launch_pdl(attn_tc, gAttn, dim3(128), 0,
                   (const __half*)pxh, (const __half*)(wq + wED), (const float*)(bq + li * DD),
                   (const __half*)(pkv + li * 2 * DD), (const __half*)(pkv + li * 2 * DD + DD), KVW,
                   (const int*)pkt, kmask, pah);

        launch_pdl(gemm_tc<false, false, true>, gD, gemm_blk, GS3,
                   (const __half*)pah, (const __half*)(wo + wED), (const float*)(bo + li * DD), (void*)pt,
                   ROWS, DD, DD, 1, (const float*)px, qmask);

        launch_pdl(ln_kernel, dim3(ROWS), dim3(128), 0,
                   (const float*)pt, (const float*)(ln1g + li * DD), (const float*)(ln1b + li * DD),
                   px, pxh);

        launch_pdl(gemm_tc<true, true, false>, gF, gemm_blk, GS3,
                   (const __half*)pxh, (const __half*)(w1 + wFD), (const float*)(b1 + li * FF), (void*)phh,
                   ROWS, FF, DD, 1, (const float*)nullptr, (const float*)nullptr);

        launch_pdl(gemm_tc<false, false, true>, gD, gemm_blk, GS3,
                   (const __half*)phh, (const __half*)(w2 + wFD), (const float*)(b2 + li * DD), (void*)pt,
                   ROWS, DD, FF, 1, (const float*)px, qmask);

        float* dst = (li == NLAYERS - 1) ? out : px;
        launch_pdl(ln_kernel, dim3(ROWS), dim3(128), 0,
                   (const float*)pt, (const float*)(ln2g + li * DD), (const float*)(ln2b + li * DD),
                   dst, pxh);
    }
}

// round 16
// speedup vs baseline: 1.3120x; 1.3120x over previous
#include <cuda_runtime.h>
#include <cuda_fp16.h>
#include <cstdint>

#define BB 4
#define LL 1024
#define DD 512
#define HH 8
#define HDIM 64
#define FF 2048
#define NLAYERS 6
#define ROWS (BB*LL)        // 4096
#define KVW (NLAYERS*2*DD)  // 6144

// ---------------- scratch (no allocation allowed) ----------------
__device__ float g_x[ROWS*DD];
__device__ float g_t[ROWS*DD];
__device__ float g_bkv[KVW];
__device__ int   g_kt[4];
__device__ __half g_xh[ROWS*DD];
__device__ __half g_kh[ROWS*DD];
__device__ __half g_ah[ROWS*DD];
__device__ __half g_hh[ROWS*FF];
__device__ __half g_kvp[(size_t)ROWS*KVW];     // all-layer K|V projections
__device__ __half g_wqh[NLAYERS*DD*DD];
__device__ __half g_woh[NLAYERS*DD*DD];
__device__ __half g_wkvh[NLAYERS*2*DD*DD];     // interleaved [li][K|V]
__device__ __half g_w1h[NLAYERS*FF*DD];
__device__ __half g_w2h[NLAYERS*FF*DD];

// ---------------- helpers ----------------
__device__ __forceinline__ uint32_t smem_u32(const void* p) {
    uint32_t a;
    asm("{ .reg .u64 t; cvta.to.shared.u64 t, %1; cvt.u32.u64 %0, t; }" : "=r"(a) : "l"(p));
    return a;
}
__device__ __forceinline__ void cp_async16(uint32_t dst, const void* src) {
    asm volatile("cp.async.cg.shared.global [%0], [%1], 16;" :: "r"(dst), "l"(src) : "memory");
}
__device__ __forceinline__ void cp_commit() {
    asm volatile("cp.async.commit_group;" ::: "memory");
}
template<int N>
__device__ __forceinline__ void cp_wait() {
    asm volatile("cp.async.wait_group %0;" :: "n"(N) : "memory");
}
__device__ __forceinline__ void ldm_x4(uint32_t* r, uint32_t addr) {
    asm volatile("ldmatrix.sync.aligned.m8n8.x4.shared.b16 {%0,%1,%2,%3}, [%4];"
                 : "=r"(r[0]), "=r"(r[1]), "=r"(r[2]), "=r"(r[3]) : "r"(addr));
}
__device__ __forceinline__ void ldm_x4_t(uint32_t* r, uint32_t addr) {
    asm volatile("ldmatrix.sync.aligned.m8n8.x4.trans.shared.b16 {%0,%1,%2,%3}, [%4];"
                 : "=r"(r[0]), "=r"(r[1]), "=r"(r[2]), "=r"(r[3]) : "r"(addr));
}
__device__ __forceinline__ void mma16816(float* c, const uint32_t* a, const uint32_t* b) {
    asm volatile(
        "mma.sync.aligned.m16n8k16.row.col.f32.f16.f16.f32 "
        "{%0,%1,%2,%3}, {%4,%5,%6,%7}, {%8,%9}, {%0,%1,%2,%3};"
        : "+f"(c[0]), "+f"(c[1]), "+f"(c[2]), "+f"(c[3])
        : "r"(a[0]), "r"(a[1]), "r"(a[2]), "r"(a[3]), "r"(b[0]), "r"(b[1]));
}
__device__ __forceinline__ uint32_t packh2(float a, float b) {
    __half2 h = __floats2half2_rn(a, b);
    return *(uint32_t*)&h;
}

// ---------------- merged startup kernel ----------------
#define PN0 393216                    // wq -> fp16
#define PN1 (PN0 + 393216)            // wo
#define PN2 (PN1 + 1572864)           // w1
#define PN3 (PN2 + 1572864)           // w2
#define PN4 (PN3 + 524288)            // key -> fp16
#define PN5 (PN4 + 524288)            // query -> fp32 + fp16
#define PN6 (PN5 + 786432)            // wkv interleave fp16
#define PREP_F4_BLOCKS (PN6 / 256)
#define PREP_BLOCKS (PREP_F4_BLOCKS + 28)

__device__ __forceinline__ void cvt_f4(const float* s, __half* d, long off) {
    float4 v = ((const float4*)s)[off];
    __half2* d2 = (__half2*)d + off * 2;
    d2[0] = __floats2half2_rn(v.x, v.y);
    d2[1] = __floats2half2_rn(v.z, v.w);
}

__global__ void prep_kernel(const float* __restrict__ wq, const float* __restrict__ wo,
                            const float* __restrict__ w1, const float* __restrict__ w2,
                            const float* __restrict__ key, const float* __restrict__ query,
                            const float* __restrict__ wk, const float* __restrict__ wv,
                            const float* __restrict__ bk, const float* __restrict__ bv,
                            const float* __restrict__ kmask,
                            __half* dwq, __half* dwo, __half* dw1, __half* dw2,
                            __half* dkey, float* dpx, __half* dpxh, __half* dwkv,
                            float* dbkv, int* dkt) {
    const int tid = threadIdx.x;
    if (blockIdx.x < PREP_F4_BLOCKS) {
        long i = (long)blockIdx.x * 256 + tid;
        if (i < PN0)      cvt_f4(wq, dwq, i);
        else if (i < PN1) cvt_f4(wo, dwo, i - PN0);
        else if (i < PN2) cvt_f4(w1, dw1, i - PN1);
        else if (i < PN3) cvt_f4(w2, dw2, i - PN2);
        else if (i < PN4) cvt_f4(key, dkey, i - PN3);
        else if (i < PN5) {
            long off = i - PN4;
            float4 v = ((const float4*)query)[off];
            ((float4*)dpx)[off] = v;
            __half2* d2 = (__half2*)dpxh + off * 2;
            d2[0] = __floats2half2_rn(v.x, v.y);
            d2[1] = __floats2half2_rn(v.z, v.w);
        } else {
            long off = i - PN5;
            int li = (int)(off / 131072), rem = (int)(off % 131072);
            const float4* src = (rem < 65536)
                ? ((const float4*)wk + (size_t)li * 65536 + rem)
                : ((const float4*)wv + (size_t)li * 65536 + (rem - 65536));
            float4 v = *src;
            __half2* d2 = (__half2*)dwkv + ((size_t)li * 131072 + rem) * 2;
            d2[0] = __floats2half2_rn(v.x, v.y);
            d2[1] = __floats2half2_rn(v.z, v.w);
        }
    } else {
        __shared__ float red[8];
        int mb = blockIdx.x - PREP_F4_BLOCKS;
        if (mb < 24) {
            int i = mb * 256 + tid;
            int li = i >> 10, r = i & 1023;
            dbkv[i] = (r < 512) ? bk[li * 512 + r] : bv[li * 512 + (r - 512)];
        } else {
            int b = mb - 24;
            float s = 0.f;
            for (int i = tid; i < LL; i += 256) s += kmask[b * LL + i];
#pragma unroll
            for (int o = 16; o > 0; o >>= 1) s += __shfl_down_sync(0xffffffffu, s, o);
            if ((tid & 31) == 0) red[tid >> 5] = s;
            __syncthreads();
            if (tid == 0) {
                float t = 0.f;
                for (int i = 0; i < 8; i++) t += red[i];
                dkt[b] = ((int)(t + 0.5f) + 63) >> 6;
            }
        }
    }
}

// ---------------- HMMA fp16 GEMM (BK=64, 3-stage cp.async pipeline) ----------------
// 128x128 tile, 256 threads (8 warps: 4m x 2n), warp tile 32x64.
// smem row stride 72 halfs = 144B -> 8 consecutive rows hit 8 distinct 16B bank
// groups mod 128B: conflict-free ldmatrix. 3 stages x 36864B = 110592B dynamic.
#define GSTR 72
#define STAGE_HALFS (128 * GSTR * 2)
#define GS3 (3 * STAGE_HALFS * 2)

template<bool RELU, bool OUTH, bool ADDRES>
__global__ __launch_bounds__(256)
void gemm_tc(const __half* __restrict__ A, const __half* __restrict__ Wt,
             const float* __restrict__ bias, void* __restrict__ Cout,
             int M, int N, int K,
             const float* __restrict__ xres, const float* __restrict__ qmask) {
    extern __shared__ char gsm[];
    const uint32_t sb = smem_u32(gsm);
    const int tid = threadIdx.x;
    const int wid = tid >> 5;
    const int lane = tid & 31;
    const int m0 = blockIdx.y * 128;
    const int n0 = blockIdx.x * 128;

    const int mwb = (wid >> 1) * 32;
    const int nwb = (wid & 1) * 64;

    float c[2][8][4];
#pragma unroll
    for (int mt = 0; mt < 2; mt++)
#pragma unroll
        for (int nt = 0; nt < 8; nt++)
#pragma unroll
            for (int i = 0; i < 4; i++) c[mt][nt][i] = 0.f;

    const int nch = K >> 6;          // BK=64 chunks

    auto load_stage = [&](int kc, int stage) {
        const uint32_t sbase = sb + stage * STAGE_HALFS * 2;
#pragma unroll
        for (int it = 0; it < 8; it++) {
            int idx = tid + it * 256;          // 0..2047
            int r = (idx & 1023) >> 3;
            int cseg = idx & 7;
            const __half* src;
            uint32_t dst;
            if (idx < 1024) {
                src = A + (size_t)(m0 + r) * K + kc * 64 + cseg * 8;
                dst = sbase + (r * GSTR + cseg * 8) * 2;
            } else {
                src = Wt + (size_t)(n0 + r) * K + kc * 64 + cseg * 8;
                dst = sbase + (128 * GSTR + r * GSTR + cseg * 8) * 2;
            }
            cp_async16(dst, src);
        }
        cp_commit();
    };

    load_stage(0, 0);
    if (nch > 1) load_stage(1, 1);

    for (int kc = 0; kc < nch; kc++) {
        const int st = kc % 3;
        if (kc + 1 < nch) cp_wait<1>();
        else              cp_wait<0>();
        __syncthreads();
        if (kc + 2 < nch) load_stage(kc + 2, (kc + 2) % 3);

        const uint32_t Ab = sb + st * STAGE_HALFS * 2;
        const uint32_t Bb = Ab + 128 * GSTR * 2;

#pragma unroll
        for (int ks = 0; ks < 4; ks++) {
            uint32_t afr[2][4], bfr[4][4];
#pragma unroll
            for (int mt = 0; mt < 2; mt++) {
                uint32_t addr = Ab + (((mwb + mt * 16 + (lane & 15)) * GSTR)
                                      + ks * 16 + ((lane >> 4) << 3)) * 2;
                ldm_x4(afr[mt], addr);
            }
#pragma unroll
            for (int np = 0; np < 4; np++) {
                uint32_t addr = Bb + (((nwb + np * 16 + (lane & 7) + ((lane >> 4) << 3)) * GSTR)
                                      + ks * 16 + (((lane >> 3) & 1) << 3)) * 2;
                ldm_x4(bfr[np], addr);
            }
#pragma unroll
            for (int mt = 0; mt < 2; mt++)
#pragma unroll
                for (int nt = 0; nt < 8; nt++)
                    mma16816(c[mt][nt], afr[mt], bfr[nt >> 1] + (nt & 1) * 2);
        }
    }

#pragma unroll
    for (int mt = 0; mt < 2; mt++) {
        const int r0 = m0 + mwb + mt * 16 + (lane >> 2);
        float qm0 = 0.f, qm1 = 0.f;
        if (ADDRES) { qm0 = qmask[r0]; qm1 = qmask[r0 + 8]; }
#pragma unroll
        for (int nt = 0; nt < 8; nt++) {
            int col = n0 + nwb + nt * 8 + (lane & 3) * 2;
            float bv0 = bias[col], bv1 = bias[col + 1];
            float v0 = c[mt][nt][0] + bv0;
            float v1 = c[mt][nt][1] + bv1;
            float v2 = c[mt][nt][2] + bv0;
            float v3 = c[mt][nt][3] + bv1;
            if (RELU) {
                v0 = fmaxf(v0, 0.f); v1 = fmaxf(v1, 0.f);
                v2 = fmaxf(v2, 0.f); v3 = fmaxf(v3, 0.f);
            }
            if (ADDRES) {
                float2 x0 = *(const float2*)(xres + (size_t)r0 * N + col);
                float2 x1 = *(const float2*)(xres + (size_t)(r0 + 8) * N + col);
                v0 = v0 * qm0 + x0.x; v1 = v1 * qm0 + x0.y;
                v2 = v2 * qm1 + x1.x; v3 = v3 * qm1 + x1.y;
            }
            if (OUTH) {
                __half* base = (__half*)Cout;
                *(__half2*)(base + (size_t)r0 * N + col)       = __floats2half2_rn(v0, v1);
                *(__half2*)(base + (size_t)(r0 + 8) * N + col) = __floats2half2_rn(v2, v3);
            } else {
                float* base = (float*)Cout;
                *(float2*)(base + (size_t)r0 * N + col)       = make_float2(v0, v1);
                *(float2*)(base + (size_t)(r0 + 8) * N + col) = make_float2(v2, v3);
            }
        }
    }
}

// ---------------- HMMA flash attention with fused Q projection ----------------
#define ATS 72

__global__ __launch_bounds__(128)
void attn_tc(const __half* __restrict__ xh, const __half* __restrict__ wqh,
             const float* __restrict__ bqp,
             const __half* __restrict__ kb0, const __half* __restrict__ vb0, int kvs,
             const int* __restrict__ ktarr, const float* __restrict__ kmask,
             __half* __restrict__ out) {
    __shared__ __half Ks[2][64 * ATS];
    __shared__ __half Vs[2][64 * ATS];
    __shared__ float MD[2][64];

    const int q0 = blockIdx.x * 64;
    const int h  = blockIdx.y;
    const int b  = blockIdx.z;
    const int tid = threadIdx.x;
    const int wid = tid >> 5;
    const int lane = tid & 31;
    const int mwb = wid * 16;
    const float scl = 0.125f;
    const int NT = ktarr[b];

    const uint32_t sK0 = smem_u32(Ks);
    const uint32_t sV0 = smem_u32(Vs);

    // ---- Q projection: Q[64,64] = x[64,512] @ Wq_head[64,512]^T ----
    const __half* xb = xh + ((size_t)(b * LL + q0)) * DD;
    const __half* wb = wqh + (size_t)h * HDIM * DD;

    auto load_qw = [&](int kc, int st) {
        const uint32_t sX = sK0 + st * 64 * ATS * 2;
        const uint32_t sW = sV0 + st * 64 * ATS * 2;
#pragma unroll
        for (int i = 0; i < 4; i++) {
            int idx = tid + i * 128;          // 0..511
            int r = (idx & 255) >> 2, c8 = (idx & 3) * 8;
            if (idx < 256) cp_async16(sX + (r * ATS + c8) * 2, xb + (size_t)r * DD + kc * 32 + c8);
            else           cp_async16(sW + (r * ATS + c8) * 2, wb + (size_t)r * DD + kc * 32 + c8);
        }
        cp_commit();
    };

    float qa[8][4];
#pragma unroll
    for (int nt = 0; nt < 8; nt++)
#pragma unroll
        for (int i = 0; i < 4; i++) qa[nt][i] = 0.f;

    load_qw(0, 0);
    for (int kc = 0; kc < 16; kc++) {
        const int st = kc & 1;
        __syncthreads();
        if (kc + 1 < 16) {
            load_qw(kc + 1, st ^ 1);
            cp_wait<1>();
        } else {
            cp_wait<0>();
        }
        __syncthreads();
        const uint32_t sX = sK0 + st * 64 * ATS * 2;
        const uint32_t sW = sV0 + st * 64 * ATS * 2;
#pragma unroll
        for (int ks = 0; ks < 2; ks++) {
            uint32_t ax[4], bw[4][4];
            {
                uint32_t addr = sX + (((mwb + (lane & 15)) * ATS) + ks * 16 + ((lane >> 4) << 3)) * 2;
                ldm_x4(ax, addr);
            }
#pragma unroll
            for (int np = 0; np < 4; np++) {
                uint32_t addr = sW + (((np * 16 + (lane & 7) + ((lane >> 4) << 3)) * ATS)
                                      + ks * 16 + (((lane >> 3) & 1) << 3)) * 2;
                ldm_x4(bw[np], addr);
            }
#pragma unroll
            for (int nt = 0; nt < 8; nt++)
                mma16816(qa[nt], ax, bw[nt >> 1] + (nt & 1) * 2);
        }
    }

    // bias + scale, repack C-frags as A-frags (C layout == A layout)
    uint32_t aq[4][4];
    {
        const int c0i = (lane & 3) * 2;
#pragma unroll
        for (int nt = 0; nt < 8; nt++) {
            int col = h * HDIM + nt * 8 + c0i;
            float b0 = bqp[col], b1 = bqp[col + 1];
            qa[nt][0] = (qa[nt][0] + b0) * scl;
            qa[nt][1] = (qa[nt][1] + b1) * scl;
            qa[nt][2] = (qa[nt][2] + b0) * scl;
            qa[nt][3] = (qa[nt][3] + b1) * scl;
        }
#pragma unroll
        for (int kc = 0; kc < 4; kc++) {
            aq[kc][0] = packh2(qa[2 * kc][0], qa[2 * kc][1]);
            aq[kc][1] = packh2(qa[2 * kc][2], qa[2 * kc][3]);
            aq[kc][2] = packh2(qa[2 * kc + 1][0], qa[2 * kc + 1][1]);
            aq[kc][3] = packh2(qa[2 * kc + 1][2], qa[2 * kc + 1][3]);
        }
    }
    __syncthreads();     // Q-proj reads done before K/V overwrite

    // ---- flash attention main loop ----
    auto load_kv = [&](int kt, int st) {
        const int k0 = kt * 64;
        const __half* kb = kb0 + ((size_t)(b * LL + k0)) * kvs + h * HDIM;
        const __half* vb = vb0 + ((size_t)(b * LL + k0)) * kvs + h * HDIM;
        const uint32_t sK = sK0 + st * 64 * ATS * 2;
        const uint32_t sV = sV0 + st * 64 * ATS * 2;
#pragma unroll
        for (int i = 0; i < 8; i++) {
            int idx = tid + i * 128;
            int r = (idx & 511) >> 3, c8 = (idx & 7) * 8;
            if (idx < 512) cp_async16(sK + (r * ATS + c8) * 2, kb + (size_t)r * kvs + c8);
            else           cp_async16(sV + (r * ATS + c8) * 2, vb + (size_t)r * kvs + c8);
        }
        if (tid < 64) MD[st][tid] = (kmask[b * LL + k0 + tid] == 0.f) ? -1e30f : 0.f;
        cp_commit();
    };

    load_kv(0, 0);

    float co[8][4];
#pragma unroll
    for (int nt = 0; nt < 8; nt++)
#pragma unroll
        for (int i = 0; i < 4; i++) co[nt][i] = 0.f;
    float m0 = -1e30f, m1 = -1e30f, l0 = 0.f, l1 = 0.f;
    const int c0 = (lane & 3) * 2;

    for (int kt = 0; kt < NT; kt++) {
        const int st = kt & 1;
        __syncthreads();
        if (kt + 1 < NT) {
            load_kv(kt + 1, st ^ 1);
            cp_wait<1>();
        } else {
            cp_wait<0>();
        }
        __syncthreads();

        const uint32_t sK = sK0 + st * 64 * ATS * 2;
        const uint32_t sV = sV0 + st * 64 * ATS * 2;

        // ---- S = Q K^T ----
        float cs[8][4];
#pragma unroll
        for (int nt = 0; nt < 8; nt++)
#pragma unroll
            for (int i = 0; i < 4; i++) cs[nt][i] = 0.f;
#pragma unroll
        for (int kc = 0; kc < 4; kc++) {
            uint32_t bk[4][4];
#pragma unroll
            for (int np = 0; np < 4; np++) {
                uint32_t addr = sK + (((np * 16 + (lane & 7) + ((lane >> 4) << 3)) * ATS)
                                      + kc * 16 + (((lane >> 3) & 1) << 3)) * 2;
                ldm_x4(bk[np], addr);
            }
#pragma unroll
            for (int nt = 0; nt < 8; nt++)
                mma16816(cs[nt], aq[kc], bk[nt >> 1] + (nt & 1) * 2);
        }

        // ---- online softmax ----
        float sv[8][4];
        float mx0 = -1e30f, mx1 = -1e30f;
#pragma unroll
        for (int nt = 0; nt < 8; nt++) {
            float a0 = MD[st][nt * 8 + c0], a1 = MD[st][nt * 8 + c0 + 1];
            sv[nt][0] = cs[nt][0] + a0;
            sv[nt][1] = cs[nt][1] + a1;
            sv[nt][2] = cs[nt][2] + a0;
            sv[nt][3] = cs[nt][3] + a1;
            mx0 = fmaxf(mx0, fmaxf(sv[nt][0], sv[nt][1]));
            mx1 = fmaxf(mx1, fmaxf(sv[nt][2], sv[nt][3]));
        }
        mx0 = fmaxf(mx0, __shfl_xor_sync(0xffffffffu, mx0, 1));
        mx0 = fmaxf(mx0, __shfl_xor_sync(0xffffffffu, mx0, 2));
        mx1 = fmaxf(mx1, __shfl_xor_sync(0xffffffffu, mx1, 1));
        mx1 = fmaxf(mx1, __shfl_xor_sync(0xffffffffu, mx1, 2));
        float mn0 = fmaxf(m0, mx0), mn1 = fmaxf(m1, mx1);
        float cr0 = __expf(m0 - mn0), cr1 = __expf(m1 - mn1);
        l0 *= cr0; l1 *= cr1;
#pragma unroll
        for (int nt = 0; nt < 8; nt++) {
            co[nt][0] *= cr0; co[nt][1] *= cr0;
            co[nt][2] *= cr1; co[nt][3] *= cr1;
        }
        float ps0 = 0.f, ps1 = 0.f;
        uint32_t ph[8][2];
#pragma unroll
        for (int nt = 0; nt < 8; nt++) {
            float p0 = __expf(sv[nt][0] - mn0);
            float p1 = __expf(sv[nt][1] - mn0);
            float p2 = __expf(sv[nt][2] - mn1);
            float p3 = __expf(sv[nt][3] - mn1);
            ps0 += p0 + p1; ps1 += p2 + p3;
            ph[nt][0] = packh2(p0, p1);
            ph[nt][1] = packh2(p2, p3);
        }
        ps0 += __shfl_xor_sync(0xffffffffu, ps0, 1);
        ps0 += __shfl_xor_sync(0xffffffffu, ps0, 2);
        ps1 += __shfl_xor_sync(0xffffffffu, ps1, 1);
        ps1 += __shfl_xor_sync(0xffffffffu, ps1, 2);
        l0 += ps0; l1 += ps1;
        m0 = mn0; m1 = mn1;

        // ---- O += P V ----
#pragma unroll
        for (int kc = 0; kc < 4; kc++) {
            uint32_t bv[4][4];
#pragma unroll
            for (int np = 0; np < 4; np++) {
                uint32_t addr = sV + (((kc * 16 + (lane & 7) + (((lane >> 3) & 1) << 3)) * ATS)
                                      + np * 16 + ((lane >> 4) << 3)) * 2;
                ldm_x4_t(bv[np], addr);
            }
            uint32_t a[4] = { ph[2 * kc][0], ph[2 * kc][1], ph[2 * kc + 1][0], ph[2 * kc + 1][1] };
#pragma unroll
            for (int nt = 0; nt < 8; nt++)
                mma16816(co[nt], a, bv[nt >> 1] + (nt & 1) * 2);
        }
    }

    float inv0 = 1.f / l0, inv1 = 1.f / l1;
    __half* ob = out + ((size_t)(b * LL + q0 + mwb)) * DD + h * HDIM;
    const int r0 = lane >> 2;
#pragma unroll
    for (int nt = 0; nt < 8; nt++) {
        int col = nt * 8 + c0;
        *(__half2*)(ob + (size_t)r0 * DD + col)       = __floats2half2_rn(co[nt][0] * inv0, co[nt][1] * inv0);
        *(__half2*)(ob + (size_t)(r0 + 8) * DD + col) = __floats2half2_rn(co[nt][2] * inv1, co[nt][3] * inv1);
    }
}

// ---------------- LayerNorm (input already has residual+mask applied) ----------------
__global__ void ln_kernel(const float* __restrict__ y,
                          const float* __restrict__ gam, const float* __restrict__ bet,
                          float* __restrict__ xout, __half* __restrict__ xouth) {
    __shared__ float red[4];
    const int row = blockIdx.x;
    const int tid = threadIdx.x;
    const float* yr = y + (size_t)row * DD;

    float vals[4];
    float s = 0.f;
#pragma unroll
    for (int i = 0; i < 4; i++) {
        int idx = tid + i * 128;
        vals[i] = yr[idx];
        s += vals[i];
    }
#pragma unroll
    for (int off = 16; off > 0; off >>= 1) s += __shfl_down_sync(0xffffffffu, s, off);
    if ((tid & 31) == 0) red[tid >> 5] = s;
    __syncthreads();
    float mean = (red[0] + red[1] + red[2] + red[3]) * (1.f / DD);

    float s2 = 0.f;
#pragma unroll
    for (int i = 0; i < 4; i++) {
        float d = vals[i] - mean;
        s2 += d * d;
    }
    __syncthreads();
#pragma unroll
    for (int off = 16; off > 0; off >>= 1) s2 += __shfl_down_sync(0xffffffffu, s2, off);
    if ((tid & 31) == 0) red[tid >> 5] = s2;
    __syncthreads();
    float var = (red[0] + red[1] + red[2] + red[3]) * (1.f / DD);
    float inv = rsqrtf(var + 1e-5f);

    float* xo = xout + (size_t)row * DD;
    __half* xoh = xouth + (size_t)row * DD;
#pragma unroll
    for (int i = 0; i < 4; i++) {
        int idx = tid + i * 128;
        float r = (vals[i] - mean) * inv * gam[idx] + bet[idx];
        xo[idx] = r;
        xoh[idx] = __float2half(r);
    }
}

// ---------------- launch ----------------
extern "C" void kernel_launch(void* const* d_in, const int* in_sizes, int n_in,
                              void* d_out, int out_size) {
    const float* query = (const float*)d_in[0];
    const float* key   = (const float*)d_in[1];
    const float* qmask = (const float*)d_in[2];
    const float* kmask = (const float*)d_in[3];
    const float* bq = (const float*)d_in[5];
    const float* bk = (const float*)d_in[7];
    const float* bv = (const float*)d_in[9];
    const float* bo = (const float*)d_in[11];
    const float* b1 = (const float*)d_in[13];
    const float* b2 = (const float*)d_in[15];
    const float* ln1g = (const float*)d_in[16];
    const float* ln1b = (const float*)d_in[17];
    const float* ln2g = (const float*)d_in[18];
    const float* ln2b = (const float*)d_in[19];
    float* out = (float*)d_out;

    float *px, *pt, *pbkv;
    int* pkt;
    __half *pxh, *pkh, *pah, *phh, *pkv;
    __half *wq, *wo, *wkv, *w1, *w2;
    cudaGetSymbolAddress((void**)&px, g_x);
    cudaGetSymbolAddress((void**)&pt, g_t);
    cudaGetSymbolAddress((void**)&pbkv, g_bkv);
    cudaGetSymbolAddress((void**)&pkt, g_kt);
    cudaGetSymbolAddress((void**)&pxh, g_xh);
    cudaGetSymbolAddress((void**)&pkh, g_kh);
    cudaGetSymbolAddress((void**)&pah, g_ah);
    cudaGetSymbolAddress((void**)&phh, g_hh);
    cudaGetSymbolAddress((void**)&pkv, g_kvp);
    cudaGetSymbolAddress((void**)&wq, g_wqh);
    cudaGetSymbolAddress((void**)&wo, g_woh);
    cudaGetSymbolAddress((void**)&wkv, g_wkvh);
    cudaGetSymbolAddress((void**)&w1, g_w1h);
    cudaGetSymbolAddress((void**)&w2, g_w2h);

    cudaFuncSetAttribute(gemm_tc<false, true, false>, cudaFuncAttributeMaxDynamicSharedMemorySize, GS3);
    cudaFuncSetAttribute(gemm_tc<false, false, true>, cudaFuncAttributeMaxDynamicSharedMemorySize, GS3);
    cudaFuncSetAttribute(gemm_tc<true, true, false>,  cudaFuncAttributeMaxDynamicSharedMemorySize, GS3);

    // ---- startup: single merged prep kernel ----
    prep_kernel<<<PREP_BLOCKS, 256>>>(
        (const float*)d_in[4], (const float*)d_in[10], (const float*)d_in[12],
        (const float*)d_in[14], key, query,
        (const float*)d_in[6], (const float*)d_in[8], bk, bv, kmask,
        wq, wo, w1, w2, pkh, px, pxh, wkv, pbkv, pkt);

    const dim3 gemm_blk(256);
    const dim3 gD(DD / 128, ROWS / 128);
    const dim3 gF(FF / 128, ROWS / 128);
    const dim3 gKV(KVW / 128, ROWS / 128);
    const dim3 gAttn(LL / 64, HH, BB);

    gemm_tc<false, true, false><<<gKV, gemm_blk, GS3>>>(pkh, wkv, pbkv, pkv, ROWS, KVW, DD, nullptr, nullptr);

    for (int li = 0; li < NLAYERS; li++) {
        const size_t wED = (size_t)li * DD * DD;
        const size_t wFD = (size_t)li * FF * DD;

        attn_tc<<<gAttn, 128>>>(pxh, wq + wED, bq + li * DD,
                                pkv + li * 2 * DD, pkv + li * 2 * DD + DD, KVW,
                                pkt, kmask, pah);

        gemm_tc<false, false, true><<<gD, gemm_blk, GS3>>>(pah, wo + wED, bo + li * DD, pt, ROWS, DD, DD, px, qmask);
        ln_kernel<<<ROWS, 128>>>(pt, ln1g + li * DD, ln1b + li * DD, px, pxh);

        gemm_tc<true, true, false><<<gF, gemm_blk, GS3>>>(pxh, w1 + wFD, b1 + li * FF, phh, ROWS, FF, DD, nullptr, nullptr);
        gemm_tc<false, false, true><<<gD, gemm_blk, GS3>>>(phh, w2 + wFD, b2 + li * DD, pt, ROWS, DD, FF, px, qmask);

        float* dst = (li == NLAYERS - 1) ? out : px;
        ln_kernel<<<ROWS, 128>>>(pt, ln2g + li * DD, ln2b + li * DD, dst, pxh);
    }
}